// round 17
// baseline (speedup 1.0000x reference)
#include <cuda_runtime.h>
#include <math.h>

// Problem dims
#define Bsz   8
#define Ssz   2048
#define DMdim 512
#define Hh    8
#define SDdim 64
#define INNER 512
#define HID   2048
#define MROWS (Bsz*Ssz)   // 16384

// ---------------- scratch (device globals: allocation-free) ----------------
__device__ float g_n [MROWS*DMdim];
__device__ float g_a [MROWS*INNER];
__device__ float g_b [MROWS*INNER];
__device__ float g_ql[MROWS*INNER];
__device__ float g_qr[MROWS*INNER];
__device__ float g_sd[MROWS*Hh];
__device__ float g_pd[MROWS*Hh];
__device__ float g_g [MROWS*INNER];
__device__ float g_r [MROWS*DMdim];
__device__ float g_l2[MROWS*DMdim];
__device__ float g_h [MROWS*HID];

// ---------------- LayerNorm ----------------
__global__ __launch_bounds__(128)
void ln_kernel(const float* __restrict__ x, const float* __restrict__ gm,
               const float* __restrict__ bt, float* __restrict__ out)
{
    int row = blockIdx.x;
    int tid = threadIdx.x;
    const float4* xr = (const float4*)(x + (size_t)row * DMdim);
    float4 v = xr[tid];
    float s  = v.x + v.y + v.z + v.w;
    float s2 = v.x*v.x + v.y*v.y + v.z*v.z + v.w*v.w;
    #pragma unroll
    for (int o = 16; o > 0; o >>= 1) {
        s  += __shfl_xor_sync(0xffffffffu, s,  o);
        s2 += __shfl_xor_sync(0xffffffffu, s2, o);
    }
    __shared__ float ss[4], ss2[4];
    int wid = tid >> 5, lane = tid & 31;
    if (lane == 0) { ss[wid] = s; ss2[wid] = s2; }
    __syncthreads();
    s  = ss[0] + ss[1] + ss[2] + ss[3];
    s2 = ss2[0] + ss2[1] + ss2[2] + ss2[3];
    float m   = s * (1.0f / DMdim);
    float var = s2 * (1.0f / DMdim) - m * m;
    float inv = rsqrtf(var + 1e-5f);
    float4 gv = ((const float4*)gm)[tid];
    float4 bv = ((const float4*)bt)[tid];
    float4 o;
    o.x = (v.x - m) * inv * gv.x + bv.x;
    o.y = (v.y - m) * inv * gv.y + bv.y;
    o.z = (v.z - m) * inv * gv.z + bv.z;
    o.w = (v.w - m) * inv * gv.w + bv.w;
    ((float4*)(out + (size_t)row * DMdim))[tid] = o;
}

// ---------------- sd/pd gates ----------------
__global__ __launch_bounds__(512)
void sdpd_kernel(const float* __restrict__ n,
                 const float* __restrict__ Wsd, const float* __restrict__ bsd,
                 const float* __restrict__ Wpd, const float* __restrict__ bpd,
                 float* __restrict__ sd, float* __restrict__ pd)
{
    int row = blockIdx.x;
    __shared__ float nr[DMdim];
    int tid = threadIdx.x;
    nr[tid] = n[(size_t)row * DMdim + tid];
    __syncthreads();
    int w = tid >> 5, lane = tid & 31;
    const float* Wt = (w < 8) ? (Wsd + (size_t)w * DMdim) : (Wpd + (size_t)(w - 8) * DMdim);
    float acc = 0.f;
    #pragma unroll
    for (int j = lane; j < DMdim; j += 32) acc += nr[j] * Wt[j];
    #pragma unroll
    for (int o = 16; o > 0; o >>= 1) acc += __shfl_xor_sync(0xffffffffu, acc, o);
    if (lane == 0) {
        int h = w & 7;
        float bias = (w < 8) ? bsd[h] : bpd[h];
        float v = 1.f / (1.f + expf(-(acc + bias)));
        if (w < 8) sd[(size_t)row * Hh + h] = v;
        else       pd[(size_t)row * Hh + h] = v;
    }
}

// ---------------- tf32 tensor-core GEMM: 4-stage cp.async + ldmatrix --------
// (R6 kernel, verbatim — proven at the legacy tf32 rate limit)
enum { EPI_TANH = 0, EPI_RES = 1, EPI_BIAS_GELU = 2, EPI_BIAS_RES = 3 };

#define ROWF   20
#define STAGEB (128*ROWF*4)
#define STAGES 4
#define GEMM_SMEM (STAGES*2*STAGEB)

__device__ __forceinline__ float fast_tanh(float x) {
    float y;
    asm("tanh.approx.f32 %0, %1;" : "=f"(y) : "f"(x));
    return y;
}
__device__ __forceinline__ void ldsm4(unsigned& r0, unsigned& r1,
                                      unsigned& r2, unsigned& r3, unsigned addr) {
    asm volatile("ldmatrix.sync.aligned.m8n8.x4.shared.b16 {%0,%1,%2,%3}, [%4];"
                 : "=r"(r0), "=r"(r1), "=r"(r2), "=r"(r3) : "r"(addr));
}

template<int EPI>
__global__ __launch_bounds__(256)
void mma_gemm_kernel(const float* __restrict__ A,
                     const float* __restrict__ w0, const float* __restrict__ w1,
                     const float* __restrict__ w2, const float* __restrict__ w3,
                     const float* __restrict__ bias, const float* __restrict__ resid,
                     float* c0, float* c1, float* c2, float* c3,
                     int N, int K)
{
    const int BK = 16;
    extern __shared__ __align__(16) float smem[];
    int z = blockIdx.z;
    const float* Bw = (z == 0) ? w0 : (z == 1) ? w1 : (z == 2) ? w2 : w3;
    float*       C  = (z == 0) ? c0 : (z == 1) ? c1 : (z == 2) ? c2 : c3;

    int tid  = threadIdx.x;
    int warp = tid >> 5, lane = tid & 31;
    int gq = lane >> 2, tg = lane & 3;
    int wm = warp & 3, wn = warp >> 2;
    int bn0 = blockIdx.x * 128, bm0 = blockIdx.y * 128;

    unsigned asA = (unsigned)__cvta_generic_to_shared(smem);
    unsigned asB = asA + STAGES * STAGEB;

    unsigned aAddr = asA + (unsigned)((wm * 32 + ((lane >> 3) & 1) * 8 + (lane & 7)) * ROWF
                                      + ((lane >> 4) & 1) * 4) * 4u;
    unsigned bAddr = asB + (unsigned)((wn * 64 + ((lane >> 4) & 1) * 8 + (lane & 7)) * ROWF
                                      + ((lane >> 3) & 1) * 4) * 4u;

    float acc[2][8][4];
    #pragma unroll
    for (int i = 0; i < 2; i++)
        #pragma unroll
        for (int j = 0; j < 8; j++)
            #pragma unroll
            for (int q = 0; q < 4; q++) acc[i][j][q] = 0.f;

    int cm = tid >> 2;
    int cc = (tid & 3) * 4;
    auto CPA = [&](int k0, int bf) {
        #pragma unroll
        for (int c = 0; c < 2; c++) {
            int m = cm + c * 64;
            unsigned da = asA + (unsigned)bf * STAGEB + (unsigned)(m * ROWF + cc) * 4u;
            const float* ga = A + (size_t)(bm0 + m) * K + k0 + cc;
            asm volatile("cp.async.cg.shared.global [%0], [%1], 16;" :: "r"(da), "l"(ga));
            unsigned db = asB + (unsigned)bf * STAGEB + (unsigned)(m * ROWF + cc) * 4u;
            const float* gb = Bw + (size_t)(bn0 + m) * K + k0 + cc;
            asm volatile("cp.async.cg.shared.global [%0], [%1], 16;" :: "r"(db), "l"(gb));
        }
        asm volatile("cp.async.commit_group;");
    };

    int NIT = K / BK;
    #pragma unroll
    for (int s = 0; s < STAGES - 1; s++) CPA(s * BK, s);

    int buf = 0;
    for (int it = 0; it < NIT; it++) {
        asm volatile("cp.async.wait_group %0;" :: "n"(STAGES - 2));
        __syncthreads();
        int nk = it + STAGES - 1;
        if (nk < NIT) CPA(nk * BK, nk & (STAGES - 1));

        unsigned bo = (unsigned)buf * STAGEB;
        #pragma unroll
        for (int s = 0; s < 2; s++) {
            unsigned so = s * 32u;
            unsigned af[2][4];
            #pragma unroll
            for (int i = 0; i < 2; i++)
                ldsm4(af[i][0], af[i][1], af[i][2], af[i][3],
                      aAddr + bo + so + (unsigned)(i * 16 * ROWF * 4));
            unsigned bfr[8][2];
            #pragma unroll
            for (int j2 = 0; j2 < 4; j2++) {
                unsigned r0, r1, r2, r3;
                ldsm4(r0, r1, r2, r3, bAddr + bo + so + (unsigned)(j2 * 16 * ROWF * 4));
                bfr[j2*2][0] = r0; bfr[j2*2][1] = r1;
                bfr[j2*2+1][0] = r2; bfr[j2*2+1][1] = r3;
            }
            #pragma unroll
            for (int i = 0; i < 2; i++)
                #pragma unroll
                for (int j = 0; j < 8; j++) {
                    asm volatile(
                        "mma.sync.aligned.m16n8k8.row.col.f32.tf32.tf32.f32 "
                        "{%0,%1,%2,%3}, {%4,%5,%6,%7}, {%8,%9}, {%0,%1,%2,%3};"
                        : "+f"(acc[i][j][0]), "+f"(acc[i][j][1]),
                          "+f"(acc[i][j][2]), "+f"(acc[i][j][3])
                        : "r"(af[i][0]), "r"(af[i][1]), "r"(af[i][2]), "r"(af[i][3]),
                          "r"(bfr[j][0]), "r"(bfr[j][1]));
                }
        }
        buf = (buf + 1) & (STAGES - 1);
    }

    #pragma unroll
    for (int i = 0; i < 2; i++) {
        int r0 = bm0 + wm * 32 + i * 16 + gq;
        #pragma unroll
        for (int j = 0; j < 8; j++) {
            int col = bn0 + wn * 64 + j * 8 + tg * 2;
            #pragma unroll
            for (int half = 0; half < 2; half++) {
                int row = r0 + half * 8;
                float v0 = acc[i][j][half * 2 + 0];
                float v1 = acc[i][j][half * 2 + 1];
                if (EPI == EPI_BIAS_GELU || EPI == EPI_BIAS_RES) {
                    v0 += bias[col]; v1 += bias[col + 1];
                }
                if (EPI == EPI_TANH) { v0 = fast_tanh(v0); v1 = fast_tanh(v1); }
                if (EPI == EPI_BIAS_GELU) {
                    v0 = 0.5f * v0 * (1.f + erff(v0 * 0.70710678118654752f));
                    v1 = 0.5f * v1 * (1.f + erff(v1 * 0.70710678118654752f));
                }
                if (EPI == EPI_RES || EPI == EPI_BIAS_RES) {
                    float2 rv = *(const float2*)(resid + (size_t)row * N + col);
                    v0 += rv.x; v1 += rv.y;
                }
                float2 o = {v0, v1};
                *(float2*)(C + (size_t)row * N + col) = o;
            }
        }
    }
}

// ---------------- pair-state scan: merged e-halves, 512 threads -------------
// grid = 64 blocks (one per (b,h)). tid>>8 = e-half, inner 256 threads use the
// proven R6 mapping (el = 32 e, dq = 8 d-slices of 8). a/ql smem tiles are
// SHARED between the halves (loaded once). 16 warps/block -> 4 warps/SMSP.
#define SCHUNK 16
__global__ __launch_bounds__(512)
void pair_scan_kernel(const float* __restrict__ a,  const float* __restrict__ bm,
                      const float* __restrict__ ql, const float* __restrict__ qr,
                      const float* __restrict__ sd, const float* __restrict__ pd,
                      float* __restrict__ g)
{
    int bh  = blockIdx.x;       // 0..63
    int tid = threadIdx.x;      // 0..511
    int eh  = tid >> 8;         // e-half
    int t8  = tid & 255;
    int el  = t8 >> 3;          // 0..31
    int e   = eh * 32 + el;     // 0..63
    int dq  = t8 & 7;           // 0..7

    __shared__ float sa [2][SCHUNK][64];   // shared across halves
    __shared__ float sq [2][SCHUNK][64];   // shared across halves
    __shared__ float sb [2][SCHUNK][64];   // full-width b
    __shared__ float sr [2][SCHUNK][64];   // full-width qr
    __shared__ float ssd[2][SCHUNK];
    __shared__ float spd[2][SCHUNK];

    size_t base0  = (size_t)(bh >> 3) * Ssz * INNER + (size_t)(bh & 7) * SDdim;
    size_t base80 = (size_t)(bh >> 3) * Ssz * Hh + (bh & 7);

    // chunk loads: 4 arrays x 16 rows x 16 float4 = 1024 float4; 2 per thread.
    // idx = tid + r*512 -> arr = idx>>8, row = (idx&255)>>4, f4 = idx&15
    bool loSd = tid < SCHUNK;
    bool loPd = tid >= 32 && tid < 32 + SCHUNK;

    float4 rv[2];
    float  rS = 0.f;

    const float* srcs0 = (tid < 256) ? a  : bm;      // r=0: arr0/arr1 -> a, ql... wait
    // arr for r=0: idx=tid: arr = tid>>8 -> 0 (a) or 1 (ql)
    // arr for r=1: idx=tid+512: arr = 2 (bm) or 3 (qr)
    const float* s0 = (tid < 256) ? a  : ql;
    const float* s1 = (tid < 256) ? bm : qr;
    int row0 = (tid & 255) >> 4, f40 = tid & 15;

    auto LOADC = [&](int c) {
        size_t bs = base0 + (size_t)c * SCHUNK * INNER;
        size_t b8 = base80 + (size_t)c * SCHUNK * Hh;
        rv[0] = *(const float4*)(s0 + bs + (size_t)row0 * INNER + f40 * 4);
        rv[1] = *(const float4*)(s1 + bs + (size_t)row0 * INNER + f40 * 4);
        if (loSd)      rS = sd[b8 + (size_t)tid * Hh];
        else if (loPd) rS = pd[b8 + (size_t)(tid - 32) * Hh];
    };
    auto STOREC = [&](int bf) {
        if (tid < 256) {
            *(float4*)&sa[bf][row0][f40 * 4] = rv[0];
            *(float4*)&sb[bf][row0][f40 * 4] = rv[1];
        } else {
            *(float4*)&sq[bf][row0][f40 * 4] = rv[0];
            *(float4*)&sr[bf][row0][f40 * 4] = rv[1];
        }
        if (loSd)      ssd[bf][tid]      = rS;
        else if (loPd) spd[bf][tid - 32] = rS;
    };

    float p[8], st[8];
    #pragma unroll
    for (int i = 0; i < 8; i++) { p[i] = 0.f; st[i] = 0.f; }

    LOADC(0);
    STOREC(0);
    __syncthreads();

    const int NC = Ssz / SCHUNK;
    int buf = 0;
    size_t gbase = base0 + e;

    for (int c = 0; c < NC; c++) {
        bool more = (c + 1) < NC;
        if (more) LOADC(c + 1);

        #pragma unroll 4
        for (int t = 0; t < SCHUNK; t++) {
            float sdv = ssd[buf][t];
            float pdv = spd[buf][t];
            float cc  = (1.f - pdv) * sb[buf][t][e];
            float4 q0 = *(const float4*)&sq[buf][t][dq * 8];
            float4 q1 = *(const float4*)&sq[buf][t][dq * 8 + 4];
            float4 a0 = *(const float4*)&sa[buf][t][dq * 8];
            float4 a1 = *(const float4*)&sa[buf][t][dq * 8 + 4];
            float qv[8] = {q0.x,q0.y,q0.z,q0.w,q1.x,q1.y,q1.z,q1.w};
            float av[8] = {a0.x,a0.y,a0.z,a0.w,a1.x,a1.y,a1.z,a1.w};

            float lacc = 0.f;
            #pragma unroll
            for (int i = 0; i < 8; i++) {
                p[i] = pdv * p[i] + cc * st[i];   // uses prev state
                lacc += p[i] * qv[i];
            }
            float om = 1.f - sdv;
            #pragma unroll
            for (int i = 0; i < 8; i++)
                st[i] = sdv * st[i] + om * av[i];

            lacc += __shfl_xor_sync(0xffffffffu, lacc, 1);
            lacc += __shfl_xor_sync(0xffffffffu, lacc, 2);
            lacc += __shfl_xor_sync(0xffffffffu, lacc, 4);
            if (dq == 0) g[gbase + (size_t)t * INNER] = lacc * sr[buf][t][e];
        }

        if (more) STOREC(buf ^ 1);
        __syncthreads();
        buf ^= 1;
        gbase += (size_t)SCHUNK * INNER;
    }
}

// ---------------- launch ----------------
extern "C" void kernel_launch(void* const* d_in, const int* in_sizes, int n_in,
                              void* d_out, int out_size)
{
    const float* x    = (const float*)d_in[0];
    const float* ng   = (const float*)d_in[1];
    const float* nb   = (const float*)d_in[2];
    const float* fng  = (const float*)d_in[3];
    const float* fnb  = (const float*)d_in[4];
    const float* Wa   = (const float*)d_in[5];
    const float* Wb   = (const float*)d_in[6];
    const float* Wql  = (const float*)d_in[7];
    const float* Wqr  = (const float*)d_in[8];
    const float* Wsd  = (const float*)d_in[9];
    const float* bsd  = (const float*)d_in[10];
    const float* Wpd  = (const float*)d_in[11];
    const float* bpd  = (const float*)d_in[12];
    const float* Wout = (const float*)d_in[13];
    const float* W1   = (const float*)d_in[14];
    const float* b1   = (const float*)d_in[15];
    const float* W2   = (const float*)d_in[16];
    const float* b2   = (const float*)d_in[17];
    float* out = (float*)d_out;

    float *pn, *pa, *pb, *pql, *pqr, *psd, *ppd, *pg, *pr, *pl2, *ph;
    cudaGetSymbolAddress((void**)&pn,  g_n);
    cudaGetSymbolAddress((void**)&pa,  g_a);
    cudaGetSymbolAddress((void**)&pb,  g_b);
    cudaGetSymbolAddress((void**)&pql, g_ql);
    cudaGetSymbolAddress((void**)&pqr, g_qr);
    cudaGetSymbolAddress((void**)&psd, g_sd);
    cudaGetSymbolAddress((void**)&ppd, g_pd);
    cudaGetSymbolAddress((void**)&pg,  g_g);
    cudaGetSymbolAddress((void**)&pr,  g_r);
    cudaGetSymbolAddress((void**)&pl2, g_l2);
    cudaGetSymbolAddress((void**)&ph,  g_h);

    cudaFuncSetAttribute(mma_gemm_kernel<EPI_TANH>,
                         cudaFuncAttributeMaxDynamicSharedMemorySize, GEMM_SMEM);
    cudaFuncSetAttribute(mma_gemm_kernel<EPI_RES>,
                         cudaFuncAttributeMaxDynamicSharedMemorySize, GEMM_SMEM);
    cudaFuncSetAttribute(mma_gemm_kernel<EPI_BIAS_GELU>,
                         cudaFuncAttributeMaxDynamicSharedMemorySize, GEMM_SMEM);
    cudaFuncSetAttribute(mma_gemm_kernel<EPI_BIAS_RES>,
                         cudaFuncAttributeMaxDynamicSharedMemorySize, GEMM_SMEM);

    // 1) n = LN(x)
    ln_kernel<<<MROWS, 128>>>(x, ng, nb, pn);

    // 2) fused tanh projections: one launch, z selects (W, out)
    dim3 gp(INNER / 128, MROWS / 128, 4);
    mma_gemm_kernel<EPI_TANH><<<gp, 256, GEMM_SMEM>>>(
        pn, Wa, Wb, Wql, Wqr, nullptr, nullptr, pa, pb, pql, pqr, INNER, DMdim);

    // 3) sigmoid gates
    sdpd_kernel<<<MROWS, 512>>>(pn, Wsd, bsd, Wpd, bpd, psd, ppd);

    // 4) pair-state scan -> g = lc * qr   (merged e-halves, 64 blocks x 512)
    pair_scan_kernel<<<64, 512>>>(pa, pb, pql, pqr, psd, ppd, pg);

    // 5) r = x + g @ Wout^T
    mma_gemm_kernel<EPI_RES><<<dim3(DMdim / 128, MROWS / 128, 1), 256, GEMM_SMEM>>>(
        pg, Wout, Wout, Wout, Wout, nullptr, x, pr, pr, pr, pr, DMdim, INNER);

    // 6) ln2 = LN(r)
    ln_kernel<<<MROWS, 128>>>(pr, fng, fnb, pl2);

    // 7) h = gelu(ln2 @ W1^T + b1)
    mma_gemm_kernel<EPI_BIAS_GELU><<<dim3(HID / 128, MROWS / 128, 1), 256, GEMM_SMEM>>>(
        pl2, W1, W1, W1, W1, b1, nullptr, ph, ph, ph, ph, HID, DMdim);

    // 8) out = r + h @ W2^T + b2
    mma_gemm_kernel<EPI_BIAS_RES><<<dim3(DMdim / 128, MROWS / 128, 1), 256, GEMM_SMEM>>>(
        ph, W2, W2, W2, W2, b2, pr, out, out, out, out, DMdim, HID);
}